// round 2
// baseline (speedup 1.0000x reference)
#include <cuda_runtime.h>
#include <cuda_bf16.h>
#include <math.h>
#include <stdint.h>

// Shapes fixed by the reference:
//   x  : (N, T, D) = (128, 512, 1024)
//   h0 : (N, H)    = (128, 1024)
//   Wx : (D, H), Wh : (H, H), b : (H)
//   out: (N, T, H) fp32
//
// Phase 0: split+transpose weights once: W[k][n] f32 -> Wt_hi/lo[n][k] bf16
// Phase 1: out = x @ Wx + b   (bf16x3 HMMA, M = 65536)
// Phase 2: out[:,t,:] = tanh(out[:,t,:] + h_{t-1} @ Wh), h read from out in place.

#define RNN_N 128
#define RNN_T 512
#define RNN_D 1024
#define RNN_H 1024

// Split, transposed weights ([n][k] layout so B mma fragments are k-contiguous)
__device__ __nv_bfloat16 g_Wxt_hi[RNN_H * RNN_D];
__device__ __nv_bfloat16 g_Wxt_lo[RNN_H * RNN_D];
__device__ __nv_bfloat16 g_Wht_hi[RNN_H * RNN_H];
__device__ __nv_bfloat16 g_Wht_lo[RNN_H * RNN_H];

// ---------------------------------------------------------------------------
// Weight convert: W (K x N, row-major) -> Wt_hi/lo (N x K, bf16 split)
// ---------------------------------------------------------------------------
__global__ __launch_bounds__(256) void convert_w_kernel(
    const float* __restrict__ W,
    __nv_bfloat16* __restrict__ Wt_hi,
    __nv_bfloat16* __restrict__ Wt_lo,
    int K, int N)
{
    __shared__ float tile[32][33];
    const int k0 = blockIdx.y * 32;
    const int n0 = blockIdx.x * 32;
    const int tx = threadIdx.x;       // 0..31
    const int ty = threadIdx.y;       // 0..7

#pragma unroll
    for (int i = 0; i < 32; i += 8)
        tile[ty + i][tx] = W[(size_t)(k0 + ty + i) * N + n0 + tx];
    __syncthreads();

#pragma unroll
    for (int i = 0; i < 32; i += 8) {
        // output element (n = n0+ty+i, k = k0+tx)
        float v = tile[tx][ty + i];
        __nv_bfloat16 h = __float2bfloat16(v);
        __nv_bfloat16 l = __float2bfloat16(v - __bfloat162float(h));
        size_t idx = (size_t)(n0 + ty + i) * K + (k0 + tx);
        Wt_hi[idx] = h;
        Wt_lo[idx] = l;
    }
}

// ---------------------------------------------------------------------------
// mma.sync m16n8k16 bf16, fp32 accum
// ---------------------------------------------------------------------------
__device__ __forceinline__ void mma_bf16(float c[4],
    uint32_t a0, uint32_t a1, uint32_t a2, uint32_t a3,
    uint32_t b0, uint32_t b1)
{
    asm volatile(
        "mma.sync.aligned.m16n8k16.row.col.f32.bf16.bf16.f32 "
        "{%0,%1,%2,%3}, {%4,%5,%6,%7}, {%8,%9}, {%0,%1,%2,%3};"
        : "+f"(c[0]), "+f"(c[1]), "+f"(c[2]), "+f"(c[3])
        : "r"(a0), "r"(a1), "r"(a2), "r"(a3), "r"(b0), "r"(b1));
}

#define LDK 40  // padded k stride (bf16 elems) for smem tiles

// Split a float4 into hi/lo bf16x2 pairs
__device__ __forceinline__ void split4(const float4 v,
    __nv_bfloat162& h0, __nv_bfloat162& h1,
    __nv_bfloat162& l0, __nv_bfloat162& l1)
{
    h0 = __floats2bfloat162_rn(v.x, v.y);
    h1 = __floats2bfloat162_rn(v.z, v.w);
    l0 = __floats2bfloat162_rn(v.x - __bfloat162float(h0.x),
                               v.y - __bfloat162float(h0.y));
    l1 = __floats2bfloat162_rn(v.z - __bfloat162float(h1.x),
                               v.w - __bfloat162float(h1.y));
}

// ---------------------------------------------------------------------------
// Phase 1: out[M][H] = x[M][D] @ Wx + b
// CTA tile 64x128, BK=32, 512 threads (16 warps, 4m x 4n), warp tile 16x32.
// ---------------------------------------------------------------------------
__global__ __launch_bounds__(512) void gemm_xw_hmma(
    const float* __restrict__ A,      // x as (M, D)
    const float* __restrict__ bias,
    float* __restrict__ C)
{
    constexpr int BM = 64, BN = 128, BK = 32;
    __shared__ __nv_bfloat16 As_hi[BM * LDK];
    __shared__ __nv_bfloat16 As_lo[BM * LDK];
    __shared__ __nv_bfloat16 Bs_hi[BN * LDK];
    __shared__ __nv_bfloat16 Bs_lo[BN * LDK];

    const int tid  = threadIdx.x;
    const int warp = tid >> 5;
    const int lane = tid & 31;
    const int g  = lane >> 2;
    const int tg = lane & 3;
    const int wm = (warp & 3) * 16;   // warp m offset
    const int wn = (warp >> 2) * 32;  // warp n offset

    const int brow = blockIdx.y * BM;
    const int bcol = blockIdx.x * BN;

    // global load indices
    const int ar = tid >> 3;          // 0..63
    const int ac = (tid & 7) * 4;     // 0..28
    const int bn = tid >> 2;          // 0..127
    const int bk = (tid & 3) * 8;     // 0,8,16,24

    const float* Aptr = A + (size_t)(brow + ar) * RNN_D + ac;
    const __nv_bfloat16* Bh = g_Wxt_hi + (size_t)(bcol + bn) * RNN_D + bk;
    const __nv_bfloat16* Bl = g_Wxt_lo + (size_t)(bcol + bn) * RNN_D + bk;

    float acc[4][4];
#pragma unroll
    for (int j = 0; j < 4; j++)
#pragma unroll
        for (int i = 0; i < 4; i++) acc[j][i] = 0.0f;

    for (int kt = 0; kt < RNN_D; kt += BK) {
        float4 av  = *(const float4*)(Aptr + kt);
        float4 bhv = *(const float4*)(Bh + kt);
        float4 blv = *(const float4*)(Bl + kt);

        __nv_bfloat162 h0, h1, l0, l1;
        split4(av, h0, h1, l0, l1);

        __syncthreads();
        *(__nv_bfloat162*)&As_hi[ar * LDK + ac]     = h0;
        *(__nv_bfloat162*)&As_hi[ar * LDK + ac + 2] = h1;
        *(__nv_bfloat162*)&As_lo[ar * LDK + ac]     = l0;
        *(__nv_bfloat162*)&As_lo[ar * LDK + ac + 2] = l1;
        *(float4*)&Bs_hi[bn * LDK + bk] = bhv;
        *(float4*)&Bs_lo[bn * LDK + bk] = blv;
        __syncthreads();

#pragma unroll
        for (int ks = 0; ks < 2; ks++) {
            const int kb = ks * 16;
            uint32_t ah[4], al[4];
            ah[0] = *(const uint32_t*)&As_hi[(wm + g    ) * LDK + kb + tg * 2];
            ah[1] = *(const uint32_t*)&As_hi[(wm + g + 8) * LDK + kb + tg * 2];
            ah[2] = *(const uint32_t*)&As_hi[(wm + g    ) * LDK + kb + tg * 2 + 8];
            ah[3] = *(const uint32_t*)&As_hi[(wm + g + 8) * LDK + kb + tg * 2 + 8];
            al[0] = *(const uint32_t*)&As_lo[(wm + g    ) * LDK + kb + tg * 2];
            al[1] = *(const uint32_t*)&As_lo[(wm + g + 8) * LDK + kb + tg * 2];
            al[2] = *(const uint32_t*)&As_lo[(wm + g    ) * LDK + kb + tg * 2 + 8];
            al[3] = *(const uint32_t*)&As_lo[(wm + g + 8) * LDK + kb + tg * 2 + 8];
#pragma unroll
            for (int j = 0; j < 4; j++) {
                const int nrow = (wn + j * 8 + g) * LDK + kb + tg * 2;
                uint32_t bh0 = *(const uint32_t*)&Bs_hi[nrow];
                uint32_t bh1 = *(const uint32_t*)&Bs_hi[nrow + 8];
                uint32_t bl0 = *(const uint32_t*)&Bs_lo[nrow];
                uint32_t bl1 = *(const uint32_t*)&Bs_lo[nrow + 8];
                mma_bf16(acc[j], ah[0], ah[1], ah[2], ah[3], bh0, bh1); // hi*hi
                mma_bf16(acc[j], ah[0], ah[1], ah[2], ah[3], bl0, bl1); // hi*lo
                mma_bf16(acc[j], al[0], al[1], al[2], al[3], bh0, bh1); // lo*hi
            }
        }
    }

    // epilogue: + bias, store
#pragma unroll
    for (int j = 0; j < 4; j++) {
        const int col = bcol + wn + j * 8 + tg * 2;
        const float b0 = __ldg(bias + col);
        const float b1 = __ldg(bias + col + 1);
        const int r0 = brow + wm + g;
        float2 o0 = make_float2(acc[j][0] + b0, acc[j][1] + b1);
        float2 o1 = make_float2(acc[j][2] + b0, acc[j][3] + b1);
        *(float2*)&C[(size_t)r0 * RNN_H + col]       = o0;
        *(float2*)&C[(size_t)(r0 + 8) * RNN_H + col] = o1;
    }
}

// ---------------------------------------------------------------------------
// Phase 2 step: out_t = tanh(out_t + h_prev @ Wh)
// CTA tile 32x64, BK=32, 128 threads (4 warps, 2m x 2n), warp tile 16x32.
// Grid (16, 4) = 64 CTAs.
// ---------------------------------------------------------------------------
__global__ __launch_bounds__(128) void rnn_step_hmma(
    const float* __restrict__ hprev, size_t hstride,
    float* __restrict__ out_t, size_t ostride)
{
    constexpr int BM = 32, BN = 64, BK = 32;
    __shared__ __nv_bfloat16 As_hi[BM * LDK];
    __shared__ __nv_bfloat16 As_lo[BM * LDK];
    __shared__ __nv_bfloat16 Bs_hi[BN * LDK];
    __shared__ __nv_bfloat16 Bs_lo[BN * LDK];

    const int tid  = threadIdx.x;
    const int warp = tid >> 5;
    const int lane = tid & 31;
    const int g  = lane >> 2;
    const int tg = lane & 3;
    const int wm = (warp & 1) * 16;
    const int wn = (warp >> 1) * 32;

    const int brow = blockIdx.y * BM;
    const int bcol = blockIdx.x * BN;

    // A loads: 32 rows x 32 k f32 = 256 float4, 2 per thread
    const int ar = tid >> 3;          // 0..15 (+16 second)
    const int ac = (tid & 7) * 4;
    // B loads: 64 rows x 32 k bf16 per matrix = 256B16x... 2 float4 per thread per matrix
    const int bn = tid >> 2;          // 0..31 (+32 second)
    const int bk = (tid & 3) * 8;

    const float* A0 = hprev + (size_t)(brow + ar) * hstride + ac;
    const float* A1 = hprev + (size_t)(brow + ar + 16) * hstride + ac;
    const __nv_bfloat16* Bh0 = g_Wht_hi + (size_t)(bcol + bn) * RNN_H + bk;
    const __nv_bfloat16* Bh1 = g_Wht_hi + (size_t)(bcol + bn + 32) * RNN_H + bk;
    const __nv_bfloat16* Bl0 = g_Wht_lo + (size_t)(bcol + bn) * RNN_H + bk;
    const __nv_bfloat16* Bl1 = g_Wht_lo + (size_t)(bcol + bn + 32) * RNN_H + bk;

    float acc[4][4];
#pragma unroll
    for (int j = 0; j < 4; j++)
#pragma unroll
        for (int i = 0; i < 4; i++) acc[j][i] = 0.0f;

    for (int kt = 0; kt < RNN_H; kt += BK) {
        float4 a0v = *(const float4*)(A0 + kt);
        float4 a1v = *(const float4*)(A1 + kt);
        float4 bh0v = *(const float4*)(Bh0 + kt);
        float4 bh1v = *(const float4*)(Bh1 + kt);
        float4 bl0v = *(const float4*)(Bl0 + kt);
        float4 bl1v = *(const float4*)(Bl1 + kt);

        __nv_bfloat162 h0, h1, l0, l1, h2, h3, l2, l3;
        split4(a0v, h0, h1, l0, l1);
        split4(a1v, h2, h3, l2, l3);

        __syncthreads();
        *(__nv_bfloat162*)&As_hi[ar * LDK + ac]            = h0;
        *(__nv_bfloat162*)&As_hi[ar * LDK + ac + 2]        = h1;
        *(__nv_bfloat162*)&As_lo[ar * LDK + ac]            = l0;
        *(__nv_bfloat162*)&As_lo[ar * LDK + ac + 2]        = l1;
        *(__nv_bfloat162*)&As_hi[(ar + 16) * LDK + ac]     = h2;
        *(__nv_bfloat162*)&As_hi[(ar + 16) * LDK + ac + 2] = h3;
        *(__nv_bfloat162*)&As_lo[(ar + 16) * LDK + ac]     = l2;
        *(__nv_bfloat162*)&As_lo[(ar + 16) * LDK + ac + 2] = l3;
        *(float4*)&Bs_hi[bn * LDK + bk]        = bh0v;
        *(float4*)&Bs_hi[(bn + 32) * LDK + bk] = bh1v;
        *(float4*)&Bs_lo[bn * LDK + bk]        = bl0v;
        *(float4*)&Bs_lo[(bn + 32) * LDK + bk] = bl1v;
        __syncthreads();

#pragma unroll
        for (int ks = 0; ks < 2; ks++) {
            const int kb = ks * 16;
            uint32_t ah[4], al[4];
            ah[0] = *(const uint32_t*)&As_hi[(wm + g    ) * LDK + kb + tg * 2];
            ah[1] = *(const uint32_t*)&As_hi[(wm + g + 8) * LDK + kb + tg * 2];
            ah[2] = *(const uint32_t*)&As_hi[(wm + g    ) * LDK + kb + tg * 2 + 8];
            ah[3] = *(const uint32_t*)&As_hi[(wm + g + 8) * LDK + kb + tg * 2 + 8];
            al[0] = *(const uint32_t*)&As_lo[(wm + g    ) * LDK + kb + tg * 2];
            al[1] = *(const uint32_t*)&As_lo[(wm + g + 8) * LDK + kb + tg * 2];
            al[2] = *(const uint32_t*)&As_lo[(wm + g    ) * LDK + kb + tg * 2 + 8];
            al[3] = *(const uint32_t*)&As_lo[(wm + g + 8) * LDK + kb + tg * 2 + 8];
#pragma unroll
            for (int j = 0; j < 4; j++) {
                const int nrow = (wn + j * 8 + g) * LDK + kb + tg * 2;
                uint32_t bh0 = *(const uint32_t*)&Bs_hi[nrow];
                uint32_t bh1 = *(const uint32_t*)&Bs_hi[nrow + 8];
                uint32_t bl0 = *(const uint32_t*)&Bs_lo[nrow];
                uint32_t bl1 = *(const uint32_t*)&Bs_lo[nrow + 8];
                mma_bf16(acc[j], ah[0], ah[1], ah[2], ah[3], bh0, bh1);
                mma_bf16(acc[j], ah[0], ah[1], ah[2], ah[3], bl0, bl1);
                mma_bf16(acc[j], al[0], al[1], al[2], al[3], bh0, bh1);
            }
        }
    }

    // epilogue: tanh(xw + acc), in place
#pragma unroll
    for (int j = 0; j < 4; j++) {
        const int col = bcol + wn + j * 8 + tg * 2;
        const int r0 = brow + wm + g;
        float* p0 = &out_t[(size_t)r0 * ostride + col];
        float* p1 = &out_t[(size_t)(r0 + 8) * ostride + col];
        float2 xw0 = *(float2*)p0;
        float2 xw1 = *(float2*)p1;
        float2 o0 = make_float2(tanhf(xw0.x + acc[j][0]), tanhf(xw0.y + acc[j][1]));
        float2 o1 = make_float2(tanhf(xw1.x + acc[j][2]), tanhf(xw1.y + acc[j][3]));
        *(float2*)p0 = o0;
        *(float2*)p1 = o1;
    }
}

// ---------------------------------------------------------------------------
// Launch
// ---------------------------------------------------------------------------
extern "C" void kernel_launch(void* const* d_in, const int* in_sizes, int n_in,
                              void* d_out, int out_size)
{
    const float* x  = (const float*)d_in[0];   // (N, T, D)
    const float* h0 = (const float*)d_in[1];   // (N, H)
    const float* Wx = (const float*)d_in[2];   // (D, H)
    const float* Wh = (const float*)d_in[3];   // (H, H)
    const float* b  = (const float*)d_in[4];   // (H)
    float* out = (float*)d_out;                // (N, T, H)

    __nv_bfloat16 *wxt_hi, *wxt_lo, *wht_hi, *wht_lo;
    cudaGetSymbolAddress((void**)&wxt_hi, g_Wxt_hi);
    cudaGetSymbolAddress((void**)&wxt_lo, g_Wxt_lo);
    cudaGetSymbolAddress((void**)&wht_hi, g_Wht_hi);
    cudaGetSymbolAddress((void**)&wht_lo, g_Wht_lo);

    // Phase 0: weight split + transpose
    {
        dim3 blk(32, 8);
        dim3 grid(RNN_H / 32, RNN_D / 32);
        convert_w_kernel<<<grid, blk>>>(Wx, wxt_hi, wxt_lo, RNN_D, RNN_H);
        convert_w_kernel<<<grid, blk>>>(Wh, wht_hi, wht_lo, RNN_H, RNN_H);
    }

    // Phase 1: out = x @ Wx + b  (M = N*T = 65536)
    {
        dim3 grid(RNN_H / 128, (RNN_N * RNN_T) / 64);  // (8, 1024)
        gemm_xw_hmma<<<grid, 512>>>(x, b, out);
    }

    // Phase 2: sequential recurrence, in place on out
    {
        dim3 grid(RNN_H / 64, RNN_N / 32);             // (16, 4) = 64 CTAs
        for (int t = 0; t < RNN_T; ++t) {
            const float* hprev;
            size_t hstride;
            if (t == 0) {
                hprev = h0;
                hstride = RNN_H;
            } else {
                hprev = out + (size_t)(t - 1) * RNN_H;    // row m at + m*T*H
                hstride = (size_t)RNN_T * RNN_H;
            }
            rnn_step_hmma<<<grid, 128>>>(hprev, hstride,
                                         out + (size_t)t * RNN_H,
                                         (size_t)RNN_T * RNN_H);
        }
    }
}

// round 3
// speedup vs baseline: 3.0948x; 3.0948x over previous
#include <cuda_runtime.h>
#include <cuda_bf16.h>
#include <math.h>
#include <stdint.h>

// Shapes fixed by the reference:
//   x  : (N, T, D) = (128, 512, 1024)
//   h0 : (N, H)    = (128, 1024)
//   Wx : (D, H), Wh : (H, H), b : (H)
//   out: (N, T, H) fp32
//
// Phase 0: split+transpose weights once: W[k][n] f32 -> Wt_hi/lo[n][k] bf16
// Phase 1: out = x @ Wx + b   (bf16x3 HMMA, M = 65536)
// Phase 2: ONE persistent kernel: 512 steps with software grid barrier,
//          Wh slice resident in smem across all steps.

#define RNN_N 128
#define RNN_T 512
#define RNN_D 1024
#define RNN_H 1024

#define P2_NCTAS 128        // 32 n-blocks x 4 m-blocks
#define P2_BM 32
#define P2_BN 32
#define P2_LDB 1032         // padded k-stride for Wh smem (elems)
#define P2_LDA 136          // padded k-stride for A chunk smem (elems)
#define P2_CHUNK 128        // k per chunk
#define OUT_RSTRIDE ((size_t)RNN_T * RNN_H)   // out row n stride

// Split, transposed weights ([n][k] layout so B mma fragments are k-contiguous)
__device__ __nv_bfloat16 g_Wxt_hi[RNN_H * RNN_D];
__device__ __nv_bfloat16 g_Wxt_lo[RNN_H * RNN_D];
__device__ __nv_bfloat16 g_Wht_hi[RNN_H * RNN_H];
__device__ __nv_bfloat16 g_Wht_lo[RNN_H * RNN_H];

// Grid barrier state
__device__ unsigned g_bar_count = 0;
__device__ volatile unsigned g_bar_gen = 0;

// ---------------------------------------------------------------------------
// Weight convert: W (K x N, row-major) -> Wt_hi/lo (N x K, bf16 split)
// ---------------------------------------------------------------------------
__global__ __launch_bounds__(256) void convert_w_kernel(
    const float* __restrict__ W,
    __nv_bfloat16* __restrict__ Wt_hi,
    __nv_bfloat16* __restrict__ Wt_lo,
    int K, int N)
{
    __shared__ float tile[32][33];
    const int k0 = blockIdx.y * 32;
    const int n0 = blockIdx.x * 32;
    const int tx = threadIdx.x;       // 0..31
    const int ty = threadIdx.y;       // 0..7

#pragma unroll
    for (int i = 0; i < 32; i += 8)
        tile[ty + i][tx] = W[(size_t)(k0 + ty + i) * N + n0 + tx];
    __syncthreads();

#pragma unroll
    for (int i = 0; i < 32; i += 8) {
        float v = tile[tx][ty + i];
        __nv_bfloat16 h = __float2bfloat16(v);
        __nv_bfloat16 l = __float2bfloat16(v - __bfloat162float(h));
        size_t idx = (size_t)(n0 + ty + i) * K + (k0 + tx);
        Wt_hi[idx] = h;
        Wt_lo[idx] = l;
    }
}

// ---------------------------------------------------------------------------
// mma.sync m16n8k16 bf16, fp32 accum
// ---------------------------------------------------------------------------
__device__ __forceinline__ void mma_bf16(float c[4],
    uint32_t a0, uint32_t a1, uint32_t a2, uint32_t a3,
    uint32_t b0, uint32_t b1)
{
    asm volatile(
        "mma.sync.aligned.m16n8k16.row.col.f32.bf16.bf16.f32 "
        "{%0,%1,%2,%3}, {%4,%5,%6,%7}, {%8,%9}, {%0,%1,%2,%3};"
        : "+f"(c[0]), "+f"(c[1]), "+f"(c[2]), "+f"(c[3])
        : "r"(a0), "r"(a1), "r"(a2), "r"(a3), "r"(b0), "r"(b1));
}

__device__ __forceinline__ void split4(const float4 v,
    __nv_bfloat162& h0, __nv_bfloat162& h1,
    __nv_bfloat162& l0, __nv_bfloat162& l1)
{
    h0 = __floats2bfloat162_rn(v.x, v.y);
    h1 = __floats2bfloat162_rn(v.z, v.w);
    l0 = __floats2bfloat162_rn(v.x - __bfloat162float(h0.x),
                               v.y - __bfloat162float(h0.y));
    l1 = __floats2bfloat162_rn(v.z - __bfloat162float(h1.x),
                               v.w - __bfloat162float(h1.y));
}

#define LDK 40  // padded k stride for phase-1 smem tiles

// ---------------------------------------------------------------------------
// Phase 1: out[M][H] = x[M][D] @ Wx + b
// CTA tile 64x128, BK=32, 512 threads (16 warps, 4m x 4n), warp tile 16x32.
// ---------------------------------------------------------------------------
__global__ __launch_bounds__(512) void gemm_xw_hmma(
    const float* __restrict__ A,
    const float* __restrict__ bias,
    float* __restrict__ C)
{
    constexpr int BM = 64, BN = 128, BK = 32;
    __shared__ __nv_bfloat16 As_hi[BM * LDK];
    __shared__ __nv_bfloat16 As_lo[BM * LDK];
    __shared__ __nv_bfloat16 Bs_hi[BN * LDK];
    __shared__ __nv_bfloat16 Bs_lo[BN * LDK];

    const int tid  = threadIdx.x;
    const int warp = tid >> 5;
    const int lane = tid & 31;
    const int g  = lane >> 2;
    const int tg = lane & 3;
    const int wm = (warp & 3) * 16;
    const int wn = (warp >> 2) * 32;

    const int brow = blockIdx.y * BM;
    const int bcol = blockIdx.x * BN;

    const int ar = tid >> 3;
    const int ac = (tid & 7) * 4;
    const int bn = tid >> 2;
    const int bk = (tid & 3) * 8;

    const float* Aptr = A + (size_t)(brow + ar) * RNN_D + ac;
    const __nv_bfloat16* Bh = g_Wxt_hi + (size_t)(bcol + bn) * RNN_D + bk;
    const __nv_bfloat16* Bl = g_Wxt_lo + (size_t)(bcol + bn) * RNN_D + bk;

    float acc[4][4];
#pragma unroll
    for (int j = 0; j < 4; j++)
#pragma unroll
        for (int i = 0; i < 4; i++) acc[j][i] = 0.0f;

    for (int kt = 0; kt < RNN_D; kt += BK) {
        float4 av  = *(const float4*)(Aptr + kt);
        float4 bhv = *(const float4*)(Bh + kt);
        float4 blv = *(const float4*)(Bl + kt);

        __nv_bfloat162 h0, h1, l0, l1;
        split4(av, h0, h1, l0, l1);

        __syncthreads();
        *(__nv_bfloat162*)&As_hi[ar * LDK + ac]     = h0;
        *(__nv_bfloat162*)&As_hi[ar * LDK + ac + 2] = h1;
        *(__nv_bfloat162*)&As_lo[ar * LDK + ac]     = l0;
        *(__nv_bfloat162*)&As_lo[ar * LDK + ac + 2] = l1;
        *(float4*)&Bs_hi[bn * LDK + bk] = bhv;
        *(float4*)&Bs_lo[bn * LDK + bk] = blv;
        __syncthreads();

#pragma unroll
        for (int ks = 0; ks < 2; ks++) {
            const int kb = ks * 16;
            uint32_t ah[4], al[4];
            ah[0] = *(const uint32_t*)&As_hi[(wm + g    ) * LDK + kb + tg * 2];
            ah[1] = *(const uint32_t*)&As_hi[(wm + g + 8) * LDK + kb + tg * 2];
            ah[2] = *(const uint32_t*)&As_hi[(wm + g    ) * LDK + kb + tg * 2 + 8];
            ah[3] = *(const uint32_t*)&As_hi[(wm + g + 8) * LDK + kb + tg * 2 + 8];
            al[0] = *(const uint32_t*)&As_lo[(wm + g    ) * LDK + kb + tg * 2];
            al[1] = *(const uint32_t*)&As_lo[(wm + g + 8) * LDK + kb + tg * 2];
            al[2] = *(const uint32_t*)&As_lo[(wm + g    ) * LDK + kb + tg * 2 + 8];
            al[3] = *(const uint32_t*)&As_lo[(wm + g + 8) * LDK + kb + tg * 2 + 8];
#pragma unroll
            for (int j = 0; j < 4; j++) {
                const int nrow = (wn + j * 8 + g) * LDK + kb + tg * 2;
                uint32_t bh0 = *(const uint32_t*)&Bs_hi[nrow];
                uint32_t bh1 = *(const uint32_t*)&Bs_hi[nrow + 8];
                uint32_t bl0 = *(const uint32_t*)&Bs_lo[nrow];
                uint32_t bl1 = *(const uint32_t*)&Bs_lo[nrow + 8];
                mma_bf16(acc[j], ah[0], ah[1], ah[2], ah[3], bh0, bh1);
                mma_bf16(acc[j], ah[0], ah[1], ah[2], ah[3], bl0, bl1);
                mma_bf16(acc[j], al[0], al[1], al[2], al[3], bh0, bh1);
            }
        }
    }

#pragma unroll
    for (int j = 0; j < 4; j++) {
        const int col = bcol + wn + j * 8 + tg * 2;
        const float b0 = __ldg(bias + col);
        const float b1 = __ldg(bias + col + 1);
        const int r0 = brow + wm + g;
        float2 o0 = make_float2(acc[j][0] + b0, acc[j][1] + b1);
        float2 o1 = make_float2(acc[j][2] + b0, acc[j][3] + b1);
        *(float2*)&C[(size_t)r0 * RNN_H + col]       = o0;
        *(float2*)&C[(size_t)(r0 + 8) * RNN_H + col] = o1;
    }
}

// ---------------------------------------------------------------------------
// Software grid barrier (all P2_NCTAS CTAs are co-resident by construction)
// ---------------------------------------------------------------------------
__device__ __forceinline__ void grid_barrier()
{
    __syncthreads();
    if (threadIdx.x == 0) {
        __threadfence();
        unsigned gen = g_bar_gen;
        unsigned old = atomicAdd(&g_bar_count, 1u);
        if (old == P2_NCTAS - 1) {
            g_bar_count = 0;
            __threadfence();
            g_bar_gen = gen + 1;
        } else {
            while (g_bar_gen == gen) { }
            __threadfence();
        }
    }
    __syncthreads();
}

// ---------------------------------------------------------------------------
// Phase 2 persistent kernel.
// Grid: 128 CTAs (1D). nblk = bx & 31 (column block of 32), mblk = bx >> 5
// (row block of 32). 256 threads = 8 warps (2m x 4n), warp tile 16x8.
// Wh slice [bcol:bcol+32][0:1024] (bf16 hi+lo) resident in smem.
// Per step: load h_prev rows [brow:brow+32] in 8 chunks of k=128,
// split to bf16 hi/lo smem (double buffered), mma, tanh epilogue in place.
// ---------------------------------------------------------------------------
__global__ __launch_bounds__(256) void rnn_persistent(
    const float* __restrict__ h0,
    float* __restrict__ out)
{
    extern __shared__ char sm[];
    __nv_bfloat16* Bs_hi = (__nv_bfloat16*)sm;                         // 32*1032
    __nv_bfloat16* Bs_lo = Bs_hi + P2_BN * P2_LDB;                     // 32*1032
    __nv_bfloat16* As_base = Bs_lo + P2_BN * P2_LDB;
    // A buffers: [buf][hi/lo][32*136]
    const int ABUF = P2_BM * P2_LDA;

    const int tid  = threadIdx.x;
    const int warp = tid >> 5;
    const int lane = tid & 31;
    const int g  = lane >> 2;
    const int tg = lane & 3;
    const int wm = (warp & 1) * 16;
    const int wn = (warp >> 1) * 8;

    const int bx   = blockIdx.x;
    const int bcol = (bx & 31) * P2_BN;
    const int brow = (bx >> 5) * P2_BM;

    // ---- Load Wh slice into smem once (hi and lo), [n][k] padded ----
    {
        const uint4* GH = (const uint4*)(g_Wht_hi + (size_t)bcol * RNN_H);
        const uint4* GL = (const uint4*)(g_Wht_lo + (size_t)bcol * RNN_H);
        // 32 rows x 128 uint4 per row = 4096 uint4 per matrix
        for (int idx = tid; idx < 4096; idx += 256) {
            const int r  = idx >> 7;
            const int k8 = (idx & 127) * 8;
            uint4 vh = GH[(size_t)r * 128 + (idx & 127)];
            uint4 vl = GL[(size_t)r * 128 + (idx & 127)];
            *(uint4*)((char*)Bs_hi + r * (P2_LDB * 2) + k8 * 2) = vh;
            *(uint4*)((char*)Bs_lo + r * (P2_LDB * 2) + k8 * 2) = vl;
        }
    }
    __syncthreads();

    // A chunk loader indices: 32 rows x 128 cols f32 per chunk
    const int lr = tid >> 3;          // row 0..31
    const int lc = (tid & 7) * 4;     // base col 0..28, +i*32

    for (int t = 0; t < RNN_T; ++t) {
        const float* hp;
        size_t hstr;
        if (t == 0) { hp = h0; hstr = RNN_H; }
        else        { hp = out + (size_t)(t - 1) * RNN_H; hstr = OUT_RSTRIDE; }
        float* ot = out + (size_t)t * RNN_H;

        // prefetch epilogue operand (written by phase 1; read-before-write in place)
        float* p0 = ot + (size_t)(brow + wm + g) * OUT_RSTRIDE + bcol + wn + tg * 2;
        float* p1 = ot + (size_t)(brow + wm + g + 8) * OUT_RSTRIDE + bcol + wn + tg * 2;
        float2 xw0 = *(float2*)p0;
        float2 xw1 = *(float2*)p1;

        float acc[4] = {0.0f, 0.0f, 0.0f, 0.0f};

        const float* arow = hp + (size_t)(brow + lr) * hstr + lc;

        float4 ra[4], rb[4];
#pragma unroll
        for (int i = 0; i < 4; i++)
            ra[i] = __ldcg((const float4*)(arow + i * 32));

#pragma unroll 2
        for (int c = 0; c < 8; ++c) {
            // prefetch next chunk
            if (c < 7) {
#pragma unroll
                for (int i = 0; i < 4; i++)
                    rb[i] = __ldcg((const float4*)(arow + (c + 1) * P2_CHUNK + i * 32));
            }
            // split current chunk into smem buffer c&1
            __nv_bfloat16* Ah = As_base + (c & 1) * (2 * ABUF);
            __nv_bfloat16* Al = Ah + ABUF;
#pragma unroll
            for (int i = 0; i < 4; i++) {
                __nv_bfloat162 h0v, h1v, l0v, l1v;
                split4(ra[i], h0v, h1v, l0v, l1v);
                const int off = lr * P2_LDA + lc + i * 32;
                *(__nv_bfloat162*)&Ah[off]     = h0v;
                *(__nv_bfloat162*)&Ah[off + 2] = h1v;
                *(__nv_bfloat162*)&Al[off]     = l0v;
                *(__nv_bfloat162*)&Al[off + 2] = l1v;
            }
            __syncthreads();

            // mma over this chunk: 8 k16 steps
#pragma unroll
            for (int ks = 0; ks < 8; ++ks) {
                const int kb = ks * 16;
                uint32_t ah[4], al[4];
                ah[0] = *(const uint32_t*)&Ah[(wm + g    ) * P2_LDA + kb + tg * 2];
                ah[1] = *(const uint32_t*)&Ah[(wm + g + 8) * P2_LDA + kb + tg * 2];
                ah[2] = *(const uint32_t*)&Ah[(wm + g    ) * P2_LDA + kb + tg * 2 + 8];
                ah[3] = *(const uint32_t*)&Ah[(wm + g + 8) * P2_LDA + kb + tg * 2 + 8];
                al[0] = *(const uint32_t*)&Al[(wm + g    ) * P2_LDA + kb + tg * 2];
                al[1] = *(const uint32_t*)&Al[(wm + g + 8) * P2_LDA + kb + tg * 2];
                al[2] = *(const uint32_t*)&Al[(wm + g    ) * P2_LDA + kb + tg * 2 + 8];
                al[3] = *(const uint32_t*)&Al[(wm + g + 8) * P2_LDA + kb + tg * 2 + 8];

                const int bkg = c * P2_CHUNK + kb + tg * 2;
                uint32_t bh0 = *(const uint32_t*)&Bs_hi[(wn + g) * P2_LDB + bkg];
                uint32_t bh1 = *(const uint32_t*)&Bs_hi[(wn + g) * P2_LDB + bkg + 8];
                uint32_t bl0 = *(const uint32_t*)&Bs_lo[(wn + g) * P2_LDB + bkg];
                uint32_t bl1 = *(const uint32_t*)&Bs_lo[(wn + g) * P2_LDB + bkg + 8];

                mma_bf16(acc, ah[0], ah[1], ah[2], ah[3], bh0, bh1); // hi*hi
                mma_bf16(acc, ah[0], ah[1], ah[2], ah[3], bl0, bl1); // hi*lo
                mma_bf16(acc, al[0], al[1], al[2], al[3], bh0, bh1); // lo*hi
            }
            // rotate register buffers
#pragma unroll
            for (int i = 0; i < 4; i++) ra[i] = rb[i];
        }

        // epilogue: tanh(xw + acc), in place
        float2 o0 = make_float2(tanhf(xw0.x + acc[0]), tanhf(xw0.y + acc[1]));
        float2 o1 = make_float2(tanhf(xw1.x + acc[2]), tanhf(xw1.y + acc[3]));
        *(float2*)p0 = o0;
        *(float2*)p1 = o1;

        grid_barrier();
    }
}

// ---------------------------------------------------------------------------
// Launch
// ---------------------------------------------------------------------------
extern "C" void kernel_launch(void* const* d_in, const int* in_sizes, int n_in,
                              void* d_out, int out_size)
{
    const float* x  = (const float*)d_in[0];   // (N, T, D)
    const float* h0 = (const float*)d_in[1];   // (N, H)
    const float* Wx = (const float*)d_in[2];   // (D, H)
    const float* Wh = (const float*)d_in[3];   // (H, H)
    const float* b  = (const float*)d_in[4];   // (H)
    float* out = (float*)d_out;                // (N, T, H)

    __nv_bfloat16 *wxt_hi, *wxt_lo, *wht_hi, *wht_lo;
    cudaGetSymbolAddress((void**)&wxt_hi, g_Wxt_hi);
    cudaGetSymbolAddress((void**)&wxt_lo, g_Wxt_lo);
    cudaGetSymbolAddress((void**)&wht_hi, g_Wht_hi);
    cudaGetSymbolAddress((void**)&wht_lo, g_Wht_lo);

    // Phase 0: weight split + transpose
    {
        dim3 blk(32, 8);
        dim3 grid(RNN_H / 32, RNN_D / 32);
        convert_w_kernel<<<grid, blk>>>(Wx, wxt_hi, wxt_lo, RNN_D, RNN_H);
        convert_w_kernel<<<grid, blk>>>(Wh, wht_hi, wht_lo, RNN_H, RNN_H);
    }

    // Phase 1: out = x @ Wx + b  (M = N*T = 65536)
    {
        dim3 grid(RNN_H / 128, (RNN_N * RNN_T) / 64);  // (8, 1024)
        gemm_xw_hmma<<<grid, 512>>>(x, b, out);
    }

    // Phase 2: single persistent kernel over all 512 steps
    {
        const int smem_bytes =
            2 * (P2_BN * P2_LDB) * (int)sizeof(__nv_bfloat16) +      // Wh hi+lo
            2 * 2 * (P2_BM * P2_LDA) * (int)sizeof(__nv_bfloat16);   // A double buf hi+lo
        cudaFuncSetAttribute(rnn_persistent,
                             cudaFuncAttributeMaxDynamicSharedMemorySize,
                             smem_bytes);
        rnn_persistent<<<P2_NCTAS, 256, smem_bytes>>>(h0, out);
    }
}

// round 4
// speedup vs baseline: 3.3120x; 1.0702x over previous
#include <cuda_runtime.h>
#include <cuda_bf16.h>
#include <math.h>
#include <stdint.h>

// Shapes fixed by the reference:
//   x  : (N, T, D) = (128, 512, 1024)
//   h0 : (N, H)    = (128, 1024)
//   Wx : (D, H), Wh : (H, H), b : (H)
//   out: (N, T, H) fp32
//
// Phase 0: split+transpose weights once: W[k][n] f32 -> Wt_hi/lo[n][k] bf16
// Phase 1: out = x @ Wx + b   (bf16x3 HMMA, M = 65536, LDG prefetch)
// Phase 2: ONE persistent kernel, 512 steps, per-row-group barriers (32 CTAs),
//          Wh slice resident in smem, 2 k-groups x (2m x 2n) warp layout.

#define RNN_N 128
#define RNN_T 512
#define RNN_D 1024
#define RNN_H 1024

#define P2_NCTAS 128        // 4 row groups x 32 column CTAs
#define P2_BM 32
#define P2_BN 32
#define P2_LDB 1032         // padded k-stride for Wh smem (elems)
#define P2_LDA 136          // padded k-stride for A chunk smem (elems)
#define P2_CHUNK 128        // k per chunk
#define P2_REDLD 34         // reduction buffer row stride (floats)
#define OUT_RSTRIDE ((size_t)RNN_T * RNN_H)   // out row n stride

// Split, transposed weights ([n][k] layout so B mma fragments are k-contiguous)
__device__ __nv_bfloat16 g_Wxt_hi[RNN_H * RNN_D];
__device__ __nv_bfloat16 g_Wxt_lo[RNN_H * RNN_D];
__device__ __nv_bfloat16 g_Wht_hi[RNN_H * RNN_H];
__device__ __nv_bfloat16 g_Wht_lo[RNN_H * RNN_H];

// Per-row-group barrier state (padded to separate cache lines)
__device__ unsigned g_bar_count[4 * 32];
__device__ volatile unsigned g_bar_gen[4 * 32];

// ---------------------------------------------------------------------------
// Weight convert: W (K x N, row-major) -> Wt_hi/lo (N x K, bf16 split)
// ---------------------------------------------------------------------------
__global__ __launch_bounds__(256) void convert_w_kernel(
    const float* __restrict__ W,
    __nv_bfloat16* __restrict__ Wt_hi,
    __nv_bfloat16* __restrict__ Wt_lo,
    int K, int N)
{
    __shared__ float tile[32][33];
    const int k0 = blockIdx.y * 32;
    const int n0 = blockIdx.x * 32;
    const int tx = threadIdx.x;       // 0..31
    const int ty = threadIdx.y;       // 0..7

#pragma unroll
    for (int i = 0; i < 32; i += 8)
        tile[ty + i][tx] = W[(size_t)(k0 + ty + i) * N + n0 + tx];
    __syncthreads();

#pragma unroll
    for (int i = 0; i < 32; i += 8) {
        float v = tile[tx][ty + i];
        __nv_bfloat16 h = __float2bfloat16(v);
        __nv_bfloat16 l = __float2bfloat16(v - __bfloat162float(h));
        size_t idx = (size_t)(n0 + ty + i) * K + (k0 + tx);
        Wt_hi[idx] = h;
        Wt_lo[idx] = l;
    }
}

// ---------------------------------------------------------------------------
// mma.sync m16n8k16 bf16, fp32 accum
// ---------------------------------------------------------------------------
__device__ __forceinline__ void mma_bf16(float c[4],
    uint32_t a0, uint32_t a1, uint32_t a2, uint32_t a3,
    uint32_t b0, uint32_t b1)
{
    asm volatile(
        "mma.sync.aligned.m16n8k16.row.col.f32.bf16.bf16.f32 "
        "{%0,%1,%2,%3}, {%4,%5,%6,%7}, {%8,%9}, {%0,%1,%2,%3};"
        : "+f"(c[0]), "+f"(c[1]), "+f"(c[2]), "+f"(c[3])
        : "r"(a0), "r"(a1), "r"(a2), "r"(a3), "r"(b0), "r"(b1));
}

__device__ __forceinline__ void split4(const float4 v,
    __nv_bfloat162& h0, __nv_bfloat162& h1,
    __nv_bfloat162& l0, __nv_bfloat162& l1)
{
    h0 = __floats2bfloat162_rn(v.x, v.y);
    h1 = __floats2bfloat162_rn(v.z, v.w);
    l0 = __floats2bfloat162_rn(v.x - __bfloat162float(h0.x),
                               v.y - __bfloat162float(h0.y));
    l1 = __floats2bfloat162_rn(v.z - __bfloat162float(h1.x),
                               v.w - __bfloat162float(h1.y));
}

#define LDK 40  // padded k stride for phase-1 smem tiles

// ---------------------------------------------------------------------------
// Phase 1: out[M][H] = x[M][D] @ Wx + b
// CTA tile 64x128, BK=32, 512 threads (16 warps, 4m x 4n), warp tile 16x32.
// Register-prefetched global loads (LDG for iter k+1 issued under mma of k).
// ---------------------------------------------------------------------------
__global__ __launch_bounds__(512) void gemm_xw_hmma(
    const float* __restrict__ A,
    const float* __restrict__ bias,
    float* __restrict__ C)
{
    constexpr int BM = 64, BN = 128, BK = 32;
    __shared__ __nv_bfloat16 As_hi[BM * LDK];
    __shared__ __nv_bfloat16 As_lo[BM * LDK];
    __shared__ __nv_bfloat16 Bs_hi[BN * LDK];
    __shared__ __nv_bfloat16 Bs_lo[BN * LDK];

    const int tid  = threadIdx.x;
    const int warp = tid >> 5;
    const int lane = tid & 31;
    const int g  = lane >> 2;
    const int tg = lane & 3;
    const int wm = (warp & 3) * 16;
    const int wn = (warp >> 2) * 32;

    const int brow = blockIdx.y * BM;
    const int bcol = blockIdx.x * BN;

    const int ar = tid >> 3;
    const int ac = (tid & 7) * 4;
    const int bn = tid >> 2;
    const int bk = (tid & 3) * 8;

    const float* Aptr = A + (size_t)(brow + ar) * RNN_D + ac;
    const __nv_bfloat16* Bh = g_Wxt_hi + (size_t)(bcol + bn) * RNN_D + bk;
    const __nv_bfloat16* Bl = g_Wxt_lo + (size_t)(bcol + bn) * RNN_D + bk;

    float acc[4][4];
#pragma unroll
    for (int j = 0; j < 4; j++)
#pragma unroll
        for (int i = 0; i < 4; i++) acc[j][i] = 0.0f;

    // preload k-slice 0
    float4 av  = *(const float4*)(Aptr);
    float4 bhv = *(const float4*)(Bh);
    float4 blv = *(const float4*)(Bl);

    for (int kt = 0; kt < RNN_D; kt += BK) {
        __nv_bfloat162 h0, h1, l0, l1;
        split4(av, h0, h1, l0, l1);

        __syncthreads();
        *(__nv_bfloat162*)&As_hi[ar * LDK + ac]     = h0;
        *(__nv_bfloat162*)&As_hi[ar * LDK + ac + 2] = h1;
        *(__nv_bfloat162*)&As_lo[ar * LDK + ac]     = l0;
        *(__nv_bfloat162*)&As_lo[ar * LDK + ac + 2] = l1;
        *(float4*)&Bs_hi[bn * LDK + bk] = bhv;
        *(float4*)&Bs_lo[bn * LDK + bk] = blv;
        __syncthreads();

        // prefetch next k-slice (overlaps with mma below)
        if (kt + BK < RNN_D) {
            av  = *(const float4*)(Aptr + kt + BK);
            bhv = *(const float4*)(Bh + kt + BK);
            blv = *(const float4*)(Bl + kt + BK);
        }

#pragma unroll
        for (int ks = 0; ks < 2; ks++) {
            const int kb = ks * 16;
            uint32_t ah[4], al[4];
            ah[0] = *(const uint32_t*)&As_hi[(wm + g    ) * LDK + kb + tg * 2];
            ah[1] = *(const uint32_t*)&As_hi[(wm + g + 8) * LDK + kb + tg * 2];
            ah[2] = *(const uint32_t*)&As_hi[(wm + g    ) * LDK + kb + tg * 2 + 8];
            ah[3] = *(const uint32_t*)&As_hi[(wm + g + 8) * LDK + kb + tg * 2 + 8];
            al[0] = *(const uint32_t*)&As_lo[(wm + g    ) * LDK + kb + tg * 2];
            al[1] = *(const uint32_t*)&As_lo[(wm + g + 8) * LDK + kb + tg * 2];
            al[2] = *(const uint32_t*)&As_lo[(wm + g    ) * LDK + kb + tg * 2 + 8];
            al[3] = *(const uint32_t*)&As_lo[(wm + g + 8) * LDK + kb + tg * 2 + 8];
#pragma unroll
            for (int j = 0; j < 4; j++) {
                const int nrow = (wn + j * 8 + g) * LDK + kb + tg * 2;
                uint32_t bh0 = *(const uint32_t*)&Bs_hi[nrow];
                uint32_t bh1 = *(const uint32_t*)&Bs_hi[nrow + 8];
                uint32_t bl0 = *(const uint32_t*)&Bs_lo[nrow];
                uint32_t bl1 = *(const uint32_t*)&Bs_lo[nrow + 8];
                mma_bf16(acc[j], ah[0], ah[1], ah[2], ah[3], bh0, bh1);
                mma_bf16(acc[j], ah[0], ah[1], ah[2], ah[3], bl0, bl1);
                mma_bf16(acc[j], al[0], al[1], al[2], al[3], bh0, bh1);
            }
        }
    }

#pragma unroll
    for (int j = 0; j < 4; j++) {
        const int col = bcol + wn + j * 8 + tg * 2;
        const float b0 = __ldg(bias + col);
        const float b1 = __ldg(bias + col + 1);
        const int r0 = brow + wm + g;
        float2 o0 = make_float2(acc[j][0] + b0, acc[j][1] + b1);
        float2 o1 = make_float2(acc[j][2] + b0, acc[j][3] + b1);
        *(float2*)&C[(size_t)r0 * RNN_H + col]       = o0;
        *(float2*)&C[(size_t)(r0 + 8) * RNN_H + col] = o1;
    }
}

// ---------------------------------------------------------------------------
// Per-row-group barrier: only the 32 CTAs sharing a row block sync.
// ---------------------------------------------------------------------------
__device__ __forceinline__ void group_barrier(int grp)
{
    __syncthreads();
    if (threadIdx.x == 0) {
        const int s = grp * 32;
        __threadfence();
        unsigned gen = g_bar_gen[s];
        unsigned old = atomicAdd(&g_bar_count[s], 1u);
        if (old == 31u) {
            g_bar_count[s] = 0;
            __threadfence();
            g_bar_gen[s] = gen + 1;
        } else {
            while (g_bar_gen[s] == gen) { }
            __threadfence();
        }
    }
    __syncthreads();
}

// ---------------------------------------------------------------------------
// Phase 2 persistent kernel.
// 128 CTAs: grp = bx>>5 (row block of 32), col = bx&31 (32-col slice).
// 256 threads = 8 warps = 2 k-groups x (2m x 2n), warp tile 16x16.
// kg0 handles k%128 in [0,64), kg1 [64,128); partials combined in smem.
// Wh slice (bf16 hi+lo, [n][k]) resident in smem across all 512 steps.
// ---------------------------------------------------------------------------
__global__ __launch_bounds__(256) void rnn_persistent(
    const float* __restrict__ h0,
    float* __restrict__ out)
{
    extern __shared__ char sm[];
    __nv_bfloat16* Bs_hi = (__nv_bfloat16*)sm;                   // 32*1032
    __nv_bfloat16* Bs_lo = Bs_hi + P2_BN * P2_LDB;               // 32*1032
    __nv_bfloat16* As_base = Bs_lo + P2_BN * P2_LDB;             // 4 * 32*136
    const int ABUF = P2_BM * P2_LDA;
    float* red = (float*)(As_base + 4 * ABUF);                   // 32*34 floats

    const int tid  = threadIdx.x;
    const int warp = tid >> 5;
    const int lane = tid & 31;
    const int g  = lane >> 2;
    const int tg = lane & 3;
    const int kg = warp >> 2;          // k-group 0/1
    const int w2 = warp & 3;
    const int wm = (w2 & 1) * 16;
    const int wn = (w2 >> 1) * 16;

    const int bx   = blockIdx.x;
    const int bcol = (bx & 31) * P2_BN;
    const int grp  = bx >> 5;
    const int brow = grp * P2_BM;

    // ---- Load Wh slice into smem once (hi and lo), [n][k] padded ----
    {
        const uint4* GH = (const uint4*)(g_Wht_hi + (size_t)bcol * RNN_H);
        const uint4* GL = (const uint4*)(g_Wht_lo + (size_t)bcol * RNN_H);
        for (int idx = tid; idx < 4096; idx += 256) {
            const int r  = idx >> 7;
            const int k8 = (idx & 127) * 8;
            uint4 vh = GH[(size_t)r * 128 + (idx & 127)];
            uint4 vl = GL[(size_t)r * 128 + (idx & 127)];
            *(uint4*)((char*)Bs_hi + r * (P2_LDB * 2) + k8 * 2) = vh;
            *(uint4*)((char*)Bs_lo + r * (P2_LDB * 2) + k8 * 2) = vl;
        }
    }
    __syncthreads();

    // A chunk loader indices: 32 rows x 128 cols f32 per chunk
    const int lr = tid >> 3;
    const int lc = (tid & 7) * 4;

    for (int t = 0; t < RNN_T; ++t) {
        const float* hp;
        size_t hstr;
        if (t == 0) { hp = h0; hstr = RNN_H; }
        else        { hp = out + (size_t)(t - 1) * RNN_H; hstr = OUT_RSTRIDE; }
        float* ot = out + (size_t)t * RNN_H;

        // epilogue operand prefetch (kg0 warps only do the epilogue)
        float2 xw[2][2];
        float* p[2][2];
        if (kg == 0) {
#pragma unroll
            for (int nb = 0; nb < 2; nb++) {
                const int col = bcol + wn + nb * 8 + tg * 2;
                p[nb][0] = ot + (size_t)(brow + wm + g)     * OUT_RSTRIDE + col;
                p[nb][1] = ot + (size_t)(brow + wm + g + 8) * OUT_RSTRIDE + col;
                xw[nb][0] = *(float2*)p[nb][0];
                xw[nb][1] = *(float2*)p[nb][1];
            }
        }

        float acc[2][4];
#pragma unroll
        for (int nb = 0; nb < 2; nb++)
#pragma unroll
            for (int i = 0; i < 4; i++) acc[nb][i] = 0.0f;

        const float* arow = hp + (size_t)(brow + lr) * hstr + lc;

        float4 ra[4], rb[4];
#pragma unroll
        for (int i = 0; i < 4; i++)
            ra[i] = __ldcg((const float4*)(arow + i * 32));

#pragma unroll 2
        for (int c = 0; c < 8; ++c) {
            if (c < 7) {
#pragma unroll
                for (int i = 0; i < 4; i++)
                    rb[i] = __ldcg((const float4*)(arow + (c + 1) * P2_CHUNK + i * 32));
            }
            __nv_bfloat16* Ah = As_base + (c & 1) * (2 * ABUF);
            __nv_bfloat16* Al = Ah + ABUF;
#pragma unroll
            for (int i = 0; i < 4; i++) {
                __nv_bfloat162 h0v, h1v, l0v, l1v;
                split4(ra[i], h0v, h1v, l0v, l1v);
                const int off = lr * P2_LDA + lc + i * 32;
                *(__nv_bfloat162*)&Ah[off]     = h0v;
                *(__nv_bfloat162*)&Ah[off + 2] = h1v;
                *(__nv_bfloat162*)&Al[off]     = l0v;
                *(__nv_bfloat162*)&Al[off + 2] = l1v;
            }
            __syncthreads();

            // this k-group's half of the chunk: 4 k16 steps
#pragma unroll
            for (int ks = 0; ks < 4; ++ks) {
                const int kb = kg * 64 + ks * 16;
                uint32_t ah[4], al[4];
                ah[0] = *(const uint32_t*)&Ah[(wm + g    ) * P2_LDA + kb + tg * 2];
                ah[1] = *(const uint32_t*)&Ah[(wm + g + 8) * P2_LDA + kb + tg * 2];
                ah[2] = *(const uint32_t*)&Ah[(wm + g    ) * P2_LDA + kb + tg * 2 + 8];
                ah[3] = *(const uint32_t*)&Ah[(wm + g + 8) * P2_LDA + kb + tg * 2 + 8];
                al[0] = *(const uint32_t*)&Al[(wm + g    ) * P2_LDA + kb + tg * 2];
                al[1] = *(const uint32_t*)&Al[(wm + g + 8) * P2_LDA + kb + tg * 2];
                al[2] = *(const uint32_t*)&Al[(wm + g    ) * P2_LDA + kb + tg * 2 + 8];
                al[3] = *(const uint32_t*)&Al[(wm + g + 8) * P2_LDA + kb + tg * 2 + 8];

                const int bkg = c * P2_CHUNK + kb + tg * 2;
#pragma unroll
                for (int nb = 0; nb < 2; nb++) {
                    const int nrow = (wn + nb * 8 + g) * P2_LDB + bkg;
                    uint32_t bh0 = *(const uint32_t*)&Bs_hi[nrow];
                    uint32_t bh1 = *(const uint32_t*)&Bs_hi[nrow + 8];
                    uint32_t bl0 = *(const uint32_t*)&Bs_lo[nrow];
                    uint32_t bl1 = *(const uint32_t*)&Bs_lo[nrow + 8];
                    mma_bf16(acc[nb], ah[0], ah[1], ah[2], ah[3], bh0, bh1); // hi*hi
                    mma_bf16(acc[nb], ah[0], ah[1], ah[2], ah[3], bl0, bl1); // hi*lo
                    mma_bf16(acc[nb], al[0], al[1], al[2], al[3], bh0, bh1); // lo*hi
                }
            }
#pragma unroll
            for (int i = 0; i < 4; i++) ra[i] = rb[i];
        }

        // combine k-groups: kg1 stores partials, kg0 adds + epilogue
        if (kg == 1) {
#pragma unroll
            for (int nb = 0; nb < 2; nb++) {
                const int col = wn + nb * 8 + tg * 2;
                *(float2*)&red[(wm + g)     * P2_REDLD + col] = make_float2(acc[nb][0], acc[nb][1]);
                *(float2*)&red[(wm + g + 8) * P2_REDLD + col] = make_float2(acc[nb][2], acc[nb][3]);
            }
        }
        __syncthreads();
        if (kg == 0) {
#pragma unroll
            for (int nb = 0; nb < 2; nb++) {
                const int col = wn + nb * 8 + tg * 2;
                float2 r0 = *(float2*)&red[(wm + g)     * P2_REDLD + col];
                float2 r1 = *(float2*)&red[(wm + g + 8) * P2_REDLD + col];
                float2 o0 = make_float2(tanhf(xw[nb][0].x + acc[nb][0] + r0.x),
                                        tanhf(xw[nb][0].y + acc[nb][1] + r0.y));
                float2 o1 = make_float2(tanhf(xw[nb][1].x + acc[nb][2] + r1.x),
                                        tanhf(xw[nb][1].y + acc[nb][3] + r1.y));
                *(float2*)p[nb][0] = o0;
                *(float2*)p[nb][1] = o1;
            }
        }

        group_barrier(grp);
    }
}

// ---------------------------------------------------------------------------
// Launch
// ---------------------------------------------------------------------------
extern "C" void kernel_launch(void* const* d_in, const int* in_sizes, int n_in,
                              void* d_out, int out_size)
{
    const float* x  = (const float*)d_in[0];   // (N, T, D)
    const float* h0 = (const float*)d_in[1];   // (N, H)
    const float* Wx = (const float*)d_in[2];   // (D, H)
    const float* Wh = (const float*)d_in[3];   // (H, H)
    const float* b  = (const float*)d_in[4];   // (H)
    float* out = (float*)d_out;                // (N, T, H)

    __nv_bfloat16 *wxt_hi, *wxt_lo, *wht_hi, *wht_lo;
    cudaGetSymbolAddress((void**)&wxt_hi, g_Wxt_hi);
    cudaGetSymbolAddress((void**)&wxt_lo, g_Wxt_lo);
    cudaGetSymbolAddress((void**)&wht_hi, g_Wht_hi);
    cudaGetSymbolAddress((void**)&wht_lo, g_Wht_lo);

    // Phase 0: weight split + transpose
    {
        dim3 blk(32, 8);
        dim3 grid(RNN_H / 32, RNN_D / 32);
        convert_w_kernel<<<grid, blk>>>(Wx, wxt_hi, wxt_lo, RNN_D, RNN_H);
        convert_w_kernel<<<grid, blk>>>(Wh, wht_hi, wht_lo, RNN_H, RNN_H);
    }

    // Phase 1: out = x @ Wx + b  (M = N*T = 65536)
    {
        dim3 grid(RNN_H / 128, (RNN_N * RNN_T) / 64);  // (8, 1024)
        gemm_xw_hmma<<<grid, 512>>>(x, b, out);
    }

    // Phase 2: single persistent kernel over all 512 steps
    {
        const int smem_bytes =
            2 * (P2_BN * P2_LDB) * (int)sizeof(__nv_bfloat16) +      // Wh hi+lo
            2 * 2 * (P2_BM * P2_LDA) * (int)sizeof(__nv_bfloat16) +  // A double buf hi+lo
            (P2_BM * P2_REDLD) * (int)sizeof(float);                 // k-group reduce
        cudaFuncSetAttribute(rnn_persistent,
                             cudaFuncAttributeMaxDynamicSharedMemorySize,
                             smem_bytes);
        rnn_persistent<<<P2_NCTAS, 256, smem_bytes>>>(h0, out);
    }
}

// round 5
// speedup vs baseline: 3.3742x; 1.0188x over previous
#include <cuda_runtime.h>
#include <cuda_bf16.h>
#include <math.h>
#include <stdint.h>

// Shapes fixed by the reference:
//   x  : (N, T, D) = (128, 512, 1024)
//   h0 : (N, H)    = (128, 1024)
//   Wx : (D, H), Wh : (H, H), b : (H)
//   out: (N, T, H) fp32

#define RNN_N 128
#define RNN_T 512
#define RNN_D 1024
#define RNN_H 1024

#define OUT_RSTRIDE ((size_t)RNN_T * RNN_H)

// Phase 2 geometry
#define P2_NCTAS 128        // 4 row groups x 32 column CTAs
#define P2_BM 32
#define P2_BN 32
#define P2_LDB 1032         // Wh smem k-stride (elems): 4-bank skew, LDSM-safe
#define P2_LDA 136          // A chunk smem k-stride (elems): 4-bank skew
#define P2_ABUF (P2_BM * P2_LDA)
#define P2_REDLD 34         // reduction buffer row stride (floats, even)

// Split, transposed weights ([n][k] layout so B fragments are k-contiguous)
__device__ __nv_bfloat16 g_Wxt_hi[RNN_H * RNN_D];
__device__ __nv_bfloat16 g_Wxt_lo[RNN_H * RNN_D];
__device__ __nv_bfloat16 g_Wht_hi[RNN_H * RNN_H];
__device__ __nv_bfloat16 g_Wht_lo[RNN_H * RNN_H];

// Per-row-group barrier state
__device__ unsigned g_bar_count[4 * 32];
__device__ volatile unsigned g_bar_gen[4 * 32];

// ---------------------------------------------------------------------------
// helpers
// ---------------------------------------------------------------------------
__device__ __forceinline__ uint32_t cvta_smem(const void* p) {
    uint32_t a;
    asm("{ .reg .u64 t; cvta.to.shared.u64 t, %1; cvt.u32.u64 %0, t; }"
        : "=r"(a) : "l"(p));
    return a;
}

__device__ __forceinline__ void ldsm_x4(uint32_t& r0, uint32_t& r1,
                                        uint32_t& r2, uint32_t& r3,
                                        uint32_t addr) {
    asm volatile("ldmatrix.sync.aligned.m8n8.x4.shared.b16 {%0,%1,%2,%3}, [%4];"
        : "=r"(r0), "=r"(r1), "=r"(r2), "=r"(r3) : "r"(addr));
}

__device__ __forceinline__ void mma_bf16(float c[4],
    uint32_t a0, uint32_t a1, uint32_t a2, uint32_t a3,
    uint32_t b0, uint32_t b1)
{
    asm volatile(
        "mma.sync.aligned.m16n8k16.row.col.f32.bf16.bf16.f32 "
        "{%0,%1,%2,%3}, {%4,%5,%6,%7}, {%8,%9}, {%0,%1,%2,%3};"
        : "+f"(c[0]), "+f"(c[1]), "+f"(c[2]), "+f"(c[3])
        : "r"(a0), "r"(a1), "r"(a2), "r"(a3), "r"(b0), "r"(b1));
}

__device__ __forceinline__ void split4(const float4 v,
    __nv_bfloat162& h0, __nv_bfloat162& h1,
    __nv_bfloat162& l0, __nv_bfloat162& l1)
{
    h0 = __floats2bfloat162_rn(v.x, v.y);
    h1 = __floats2bfloat162_rn(v.z, v.w);
    l0 = __floats2bfloat162_rn(v.x - __bfloat162float(h0.x),
                               v.y - __bfloat162float(h0.y));
    l1 = __floats2bfloat162_rn(v.z - __bfloat162float(h1.x),
                               v.w - __bfloat162float(h1.y));
}

#define NAMED_BAR(id) asm volatile("bar.sync %0, 128;" :: "r"(id) : "memory")

// ---------------------------------------------------------------------------
// Weight convert: W (K x N, row-major) -> Wt_hi/lo (N x K, bf16 split)
// ---------------------------------------------------------------------------
__global__ __launch_bounds__(256) void convert_w_kernel(
    const float* __restrict__ W,
    __nv_bfloat16* __restrict__ Wt_hi,
    __nv_bfloat16* __restrict__ Wt_lo,
    int K, int N)
{
    __shared__ float tile[32][33];
    const int k0 = blockIdx.y * 32;
    const int n0 = blockIdx.x * 32;
    const int tx = threadIdx.x;
    const int ty = threadIdx.y;

#pragma unroll
    for (int i = 0; i < 32; i += 8)
        tile[ty + i][tx] = W[(size_t)(k0 + ty + i) * N + n0 + tx];
    __syncthreads();

#pragma unroll
    for (int i = 0; i < 32; i += 8) {
        float v = tile[tx][ty + i];
        __nv_bfloat16 h = __float2bfloat16(v);
        __nv_bfloat16 l = __float2bfloat16(v - __bfloat162float(h));
        size_t idx = (size_t)(n0 + ty + i) * K + (k0 + tx);
        Wt_hi[idx] = h;
        Wt_lo[idx] = l;
    }
}

// ---------------------------------------------------------------------------
// Phase 1: out[M][H] = x[M][D] @ Wx + b
// CTA 64x128, BK=32, 512 thr (16 warps 4m x 4n), warp tile 16x32.
// Double-buffered smem, LDSM fragment loads, 2-deep LDG pipeline.
// ---------------------------------------------------------------------------
#define P1_LDK 40
#define P1_ABUF (64 * P1_LDK)      // elems per A matrix per buffer
#define P1_BBUF (128 * P1_LDK)

__global__ __launch_bounds__(512) void gemm_xw_hmma(
    const float* __restrict__ A,
    const float* __restrict__ bias,
    float* __restrict__ C)
{
    extern __shared__ __nv_bfloat16 p1sm[];
    // layout: AsHi[2] | AsLo[2] | BsHi[2] | BsLo[2]
    __nv_bfloat16* AsHi = p1sm;
    __nv_bfloat16* AsLo = AsHi + 2 * P1_ABUF;
    __nv_bfloat16* BsHi = AsLo + 2 * P1_ABUF;
    __nv_bfloat16* BsLo = BsHi + 2 * P1_BBUF;

    const int tid  = threadIdx.x;
    const int warp = tid >> 5;
    const int lane = tid & 31;
    const int g  = lane >> 2;
    const int tg = lane & 3;
    const int wm = (warp & 3) * 16;
    const int wn = (warp >> 2) * 32;

    const int brow = blockIdx.y * 64;
    const int bcol = blockIdx.x * 128;

    // loader indices
    const int ar = tid >> 3;          // 0..63
    const int ac = (tid & 7) * 4;     // 0..28
    const int bn = tid >> 2;          // 0..127
    const int bk8 = (tid & 3) * 8;    // 0,8,16,24

    const float* Ap = A + (size_t)(brow + ar) * RNN_D + ac;
    const __nv_bfloat16* Bhp = g_Wxt_hi + (size_t)(bcol + bn) * RNN_D + bk8;
    const __nv_bfloat16* Blp = g_Wxt_lo + (size_t)(bcol + bn) * RNN_D + bk8;

    // LDSM base addresses (buffer 0); add buf*bytes for buffer 1
    const uint32_t aHi0 = cvta_smem(AsHi) +
        (((wm + (lane & 15)) * P1_LDK + ((lane >> 4) & 1) * 8) * 2);
    const uint32_t aLo0 = aHi0 + 2 * P1_ABUF * 2 /*bytes: AsLo-AsHi*/;
    const uint32_t bHi0 = cvta_smem(BsHi) +
        (((wn + (lane & 7) + ((lane >> 4) & 1) * 8) * P1_LDK +
          ((lane >> 3) & 1) * 8) * 2);
    const uint32_t bLo0 = bHi0 + 2 * P1_BBUF * 2;

    float acc[4][4];
#pragma unroll
    for (int j = 0; j < 4; j++)
#pragma unroll
        for (int i = 0; i < 4; i++) acc[j][i] = 0.0f;

    // prologue: k-slice 0 -> buf0; preload slice 1 regs
    {
        float4 av = *(const float4*)Ap;
        uint4  bh = *(const uint4*)Bhp;
        uint4  bl = *(const uint4*)Blp;
        __nv_bfloat162 h0, h1, l0, l1;
        split4(av, h0, h1, l0, l1);
        uint2 hv; hv.x = *(uint32_t*)&h0; hv.y = *(uint32_t*)&h1;
        uint2 lv; lv.x = *(uint32_t*)&l0; lv.y = *(uint32_t*)&l1;
        *(uint2*)&AsHi[ar * P1_LDK + ac] = hv;
        *(uint2*)&AsLo[ar * P1_LDK + ac] = lv;
        *(uint4*)&BsHi[bn * P1_LDK + bk8] = bh;
        *(uint4*)&BsLo[bn * P1_LDK + bk8] = bl;
    }
    float4 avn = *(const float4*)(Ap + 32);
    uint4  bhn = *(const uint4*)(Bhp + 32);
    uint4  bln = *(const uint4*)(Blp + 32);
    __syncthreads();

    for (int i = 0; i < 32; ++i) {
        // prefetch slice i+2
        float4 av2; uint4 bh2, bl2;
        if (i + 2 < 32) {
            av2 = *(const float4*)(Ap + (i + 2) * 32);
            bh2 = *(const uint4*)(Bhp + (i + 2) * 32);
            bl2 = *(const uint4*)(Blp + (i + 2) * 32);
        }

        // mma on buffer i&1
        const uint32_t aoff = (i & 1) * (P1_ABUF * 2);
        const uint32_t boff = (i & 1) * (P1_BBUF * 2);
#pragma unroll
        for (int ks = 0; ks < 2; ++ks) {
            uint32_t ah0, ah1, ah2, ah3, al0, al1, al2, al3;
            ldsm_x4(ah0, ah1, ah2, ah3, aHi0 + aoff + ks * 32);
            ldsm_x4(al0, al1, al2, al3, aLo0 + aoff + ks * 32);
#pragma unroll
            for (int pr = 0; pr < 2; ++pr) {
                uint32_t bh0, bh1, bh2_, bh3_, bl0, bl1, bl2_, bl3_;
                ldsm_x4(bh0, bh1, bh2_, bh3_, bHi0 + boff + pr * (16 * P1_LDK * 2) + ks * 32);
                ldsm_x4(bl0, bl1, bl2_, bl3_, bLo0 + boff + pr * (16 * P1_LDK * 2) + ks * 32);
                mma_bf16(acc[2 * pr],     ah0, ah1, ah2, ah3, bh0, bh1);
                mma_bf16(acc[2 * pr],     ah0, ah1, ah2, ah3, bl0, bl1);
                mma_bf16(acc[2 * pr],     al0, al1, al2, al3, bh0, bh1);
                mma_bf16(acc[2 * pr + 1], ah0, ah1, ah2, ah3, bh2_, bh3_);
                mma_bf16(acc[2 * pr + 1], ah0, ah1, ah2, ah3, bl2_, bl3_);
                mma_bf16(acc[2 * pr + 1], al0, al1, al2, al3, bh2_, bh3_);
            }
        }

        // STS slice i+1 into buffer (i+1)&1
        if (i + 1 < 32) {
            const int buf = (i + 1) & 1;
            __nv_bfloat162 h0, h1, l0, l1;
            split4(avn, h0, h1, l0, l1);
            uint2 hv; hv.x = *(uint32_t*)&h0; hv.y = *(uint32_t*)&h1;
            uint2 lv; lv.x = *(uint32_t*)&l0; lv.y = *(uint32_t*)&l1;
            *(uint2*)&AsHi[buf * P1_ABUF + ar * P1_LDK + ac] = hv;
            *(uint2*)&AsLo[buf * P1_ABUF + ar * P1_LDK + ac] = lv;
            *(uint4*)&BsHi[buf * P1_BBUF + bn * P1_LDK + bk8] = bhn;
            *(uint4*)&BsLo[buf * P1_BBUF + bn * P1_LDK + bk8] = bln;
        }
        avn = av2; bhn = bh2; bln = bl2;
        __syncthreads();
    }

    // epilogue: + bias, store
#pragma unroll
    for (int j = 0; j < 4; j++) {
        const int col = bcol + wn + j * 8 + tg * 2;
        const float b0 = __ldg(bias + col);
        const float b1 = __ldg(bias + col + 1);
        const int r0 = brow + wm + g;
        float2 o0 = make_float2(acc[j][0] + b0, acc[j][1] + b1);
        float2 o1 = make_float2(acc[j][2] + b0, acc[j][3] + b1);
        *(float2*)&C[(size_t)r0 * RNN_H + col]       = o0;
        *(float2*)&C[(size_t)(r0 + 8) * RNN_H + col] = o1;
    }
}

// ---------------------------------------------------------------------------
// Per-row-group barrier: only the 32 CTAs sharing a row block sync.
// ---------------------------------------------------------------------------
__device__ __forceinline__ void group_barrier(int grp)
{
    __syncthreads();
    if (threadIdx.x == 0) {
        const int s = grp * 32;
        __threadfence();
        unsigned gen = g_bar_gen[s];
        unsigned old = atomicAdd(&g_bar_count[s], 1u);
        if (old == 31u) {
            g_bar_count[s] = 0;
            __threadfence();
            g_bar_gen[s] = gen + 1;
        } else {
            while (g_bar_gen[s] == gen) { }
            __threadfence();
        }
    }
    __syncthreads();
}

// ---------------------------------------------------------------------------
// Phase 2 persistent kernel.
// 128 CTAs: grp = bx>>5 (32-row block), col = bx&31 (32-col slice).
// 512 threads = 16 warps = 4 k-groups x (2m x 2n); warp tile 16x16.
// Each k-group owns k-range [kg*256,(kg+1)*256), private A smem buffer,
// named-barrier sync. Partials summed in smem, epilogue by all 512 threads.
// ---------------------------------------------------------------------------
__global__ __launch_bounds__(512) void rnn_persistent(
    const float* __restrict__ h0,
    float* __restrict__ out)
{
    extern __shared__ char sm[];
    __nv_bfloat16* Bs_hi = (__nv_bfloat16*)sm;                 // 32*1032
    __nv_bfloat16* Bs_lo = Bs_hi + P2_BN * P2_LDB;
    __nv_bfloat16* A_all = Bs_lo + P2_BN * P2_LDB;             // 4 kg x (hi+lo)
    float* red = (float*)(A_all + 4 * 2 * P2_ABUF);            // 4 x 32*34

    const int tid  = threadIdx.x;
    const int warp = tid >> 5;
    const int lane = tid & 31;
    const int g  = lane >> 2;
    const int tg = lane & 3;
    const int kg = warp >> 2;          // 0..3
    const int w2 = warp & 3;
    const int wm = (w2 & 1) * 16;
    const int wn = (w2 >> 1) * 16;

    const int bx   = blockIdx.x;
    const int bcol = (bx & 31) * P2_BN;
    const int grp  = bx >> 5;
    const int brow = grp * P2_BM;

    // ---- Load Wh slice into smem once ----
    {
        const uint4* GH = (const uint4*)(g_Wht_hi + (size_t)bcol * RNN_H);
        const uint4* GL = (const uint4*)(g_Wht_lo + (size_t)bcol * RNN_H);
        for (int idx = tid; idx < 4096; idx += 512) {
            const int r  = idx >> 7;
            const int k8 = (idx & 127) * 8;
            uint4 vh = GH[(size_t)r * 128 + (idx & 127)];
            uint4 vl = GL[(size_t)r * 128 + (idx & 127)];
            *(uint4*)((char*)Bs_hi + r * (P2_LDB * 2) + k8 * 2) = vh;
            *(uint4*)((char*)Bs_lo + r * (P2_LDB * 2) + k8 * 2) = vl;
        }
    }
    __syncthreads();

    __nv_bfloat16* Ah = A_all + kg * (2 * P2_ABUF);
    __nv_bfloat16* Al = Ah + P2_ABUF;

    // LDSM base addresses
    const uint32_t aHi = cvta_smem(Ah) +
        (((wm + (lane & 15)) * P2_LDA + ((lane >> 4) & 1) * 8) * 2);
    const uint32_t aLo = aHi + P2_ABUF * 2;
    const uint32_t bHi = cvta_smem(Bs_hi) +
        (((wn + (lane & 7) + ((lane >> 4) & 1) * 8) * P2_LDB +
          ((lane >> 3) & 1) * 8) * 2);
    const uint32_t bLo = bHi + (P2_BN * P2_LDB) * 2;

    // A loader indices within k-group (128 threads)
    const int tkg = tid & 127;
    const int lr  = tkg >> 2;          // 0..31
    const int lc4 = tkg & 3;           // float4 slot

    const int barid = 1 + kg;

    // epilogue indices
    const int erow = tid >> 4;         // 0..31
    const int ecol = (tid & 15) * 2;   // 0..30

    for (int t = 0; t < RNN_T; ++t) {
        const float* hp;
        size_t hstr;
        if (t == 0) { hp = h0; hstr = RNN_H; }
        else        { hp = out + (size_t)(t - 1) * RNN_H; hstr = OUT_RSTRIDE; }
        float* ot = out + (size_t)t * RNN_H;

        // prefetch xw (this CTA's own tile)
        float2 xw = __ldcg((const float2*)(ot + (size_t)(brow + erow) * OUT_RSTRIDE
                                           + bcol + ecol));

        const float* arow = hp + (size_t)(brow + lr) * hstr + kg * 256 + lc4 * 4;

        // chunk 0 loads
        float4 ra[8];
#pragma unroll
        for (int j = 0; j < 8; j++)
            ra[j] = __ldcg((const float4*)(arow + j * 16));

        float acc[2][4];
#pragma unroll
        for (int nb = 0; nb < 2; nb++)
#pragma unroll
            for (int i = 0; i < 4; i++) acc[nb][i] = 0.0f;

        // split+STS chunk 0
#pragma unroll
        for (int j = 0; j < 8; j++) {
            __nv_bfloat162 h0v, h1v, l0v, l1v;
            split4(ra[j], h0v, h1v, l0v, l1v);
            const int off = lr * P2_LDA + lc4 * 4 + j * 16;
            uint2 hv; hv.x = *(uint32_t*)&h0v; hv.y = *(uint32_t*)&h1v;
            uint2 lv; lv.x = *(uint32_t*)&l0v; lv.y = *(uint32_t*)&l1v;
            *(uint2*)&Ah[off] = hv;
            *(uint2*)&Al[off] = lv;
        }
        NAMED_BAR(barid);

        // chunk 1 loads (hidden under chunk-0 mma)
        float4 rb[8];
#pragma unroll
        for (int j = 0; j < 8; j++)
            rb[j] = __ldcg((const float4*)(arow + 128 + j * 16));

        // mma chunk 0
        {
            const uint32_t bbase = (uint32_t)(kg * 256) * 2;
#pragma unroll
            for (int ks = 0; ks < 8; ++ks) {
                uint32_t ah0, ah1, ah2, ah3, al0, al1, al2, al3;
                ldsm_x4(ah0, ah1, ah2, ah3, aHi + ks * 32);
                ldsm_x4(al0, al1, al2, al3, aLo + ks * 32);
                uint32_t bh0, bh1, bh2, bh3, bl0, bl1, bl2, bl3;
                ldsm_x4(bh0, bh1, bh2, bh3, bHi + bbase + ks * 32);
                ldsm_x4(bl0, bl1, bl2, bl3, bLo + bbase + ks * 32);
                mma_bf16(acc[0], ah0, ah1, ah2, ah3, bh0, bh1);
                mma_bf16(acc[0], ah0, ah1, ah2, ah3, bl0, bl1);
                mma_bf16(acc[0], al0, al1, al2, al3, bh0, bh1);
                mma_bf16(acc[1], ah0, ah1, ah2, ah3, bh2, bh3);
                mma_bf16(acc[1], ah0, ah1, ah2, ah3, bl2, bl3);
                mma_bf16(acc[1], al0, al1, al2, al3, bh2, bh3);
            }
        }
        NAMED_BAR(barid);

        // split+STS chunk 1
#pragma unroll
        for (int j = 0; j < 8; j++) {
            __nv_bfloat162 h0v, h1v, l0v, l1v;
            split4(rb[j], h0v, h1v, l0v, l1v);
            const int off = lr * P2_LDA + lc4 * 4 + j * 16;
            uint2 hv; hv.x = *(uint32_t*)&h0v; hv.y = *(uint32_t*)&h1v;
            uint2 lv; lv.x = *(uint32_t*)&l0v; lv.y = *(uint32_t*)&l1v;
            *(uint2*)&Ah[off] = hv;
            *(uint2*)&Al[off] = lv;
        }
        NAMED_BAR(barid);

        // mma chunk 1
        {
            const uint32_t bbase = (uint32_t)(kg * 256 + 128) * 2;
#pragma unroll
            for (int ks = 0; ks < 8; ++ks) {
                uint32_t ah0, ah1, ah2, ah3, al0, al1, al2, al3;
                ldsm_x4(ah0, ah1, ah2, ah3, aHi + ks * 32);
                ldsm_x4(al0, al1, al2, al3, aLo + ks * 32);
                uint32_t bh0, bh1, bh2, bh3, bl0, bl1, bl2, bl3;
                ldsm_x4(bh0, bh1, bh2, bh3, bHi + bbase + ks * 32);
                ldsm_x4(bl0, bl1, bl2, bl3, bLo + bbase + ks * 32);
                mma_bf16(acc[0], ah0, ah1, ah2, ah3, bh0, bh1);
                mma_bf16(acc[0], ah0, ah1, ah2, ah3, bl0, bl1);
                mma_bf16(acc[0], al0, al1, al2, al3, bh0, bh1);
                mma_bf16(acc[1], ah0, ah1, ah2, ah3, bh2, bh3);
                mma_bf16(acc[1], ah0, ah1, ah2, ah3, bl2, bl3);
                mma_bf16(acc[1], al0, al1, al2, al3, bh2, bh3);
            }
        }

        // store partials to reduction buffers
        {
            float* rg = red + kg * (P2_BM * P2_REDLD);
#pragma unroll
            for (int nb = 0; nb < 2; nb++) {
                const int col = wn + nb * 8 + tg * 2;
                *(float2*)&rg[(wm + g)     * P2_REDLD + col] =
                    make_float2(acc[nb][0], acc[nb][1]);
                *(float2*)&rg[(wm + g + 8) * P2_REDLD + col] =
                    make_float2(acc[nb][2], acc[nb][3]);
            }
        }
        __syncthreads();

        // epilogue: all 512 threads, 2 elems each
        {
            float sx = xw.x, sy = xw.y;
#pragma unroll
            for (int q = 0; q < 4; q++) {
                float2 v = *(float2*)&red[q * (P2_BM * P2_REDLD)
                                          + erow * P2_REDLD + ecol];
                sx += v.x; sy += v.y;
            }
            float2 o = make_float2(tanhf(sx), tanhf(sy));
            *(float2*)(ot + (size_t)(brow + erow) * OUT_RSTRIDE + bcol + ecol) = o;
        }

        group_barrier(grp);
    }
}

// ---------------------------------------------------------------------------
// Launch
// ---------------------------------------------------------------------------
extern "C" void kernel_launch(void* const* d_in, const int* in_sizes, int n_in,
                              void* d_out, int out_size)
{
    const float* x  = (const float*)d_in[0];   // (N, T, D)
    const float* h0 = (const float*)d_in[1];   // (N, H)
    const float* Wx = (const float*)d_in[2];   // (D, H)
    const float* Wh = (const float*)d_in[3];   // (H, H)
    const float* b  = (const float*)d_in[4];   // (H)
    float* out = (float*)d_out;                // (N, T, H)

    __nv_bfloat16 *wxt_hi, *wxt_lo, *wht_hi, *wht_lo;
    cudaGetSymbolAddress((void**)&wxt_hi, g_Wxt_hi);
    cudaGetSymbolAddress((void**)&wxt_lo, g_Wxt_lo);
    cudaGetSymbolAddress((void**)&wht_hi, g_Wht_hi);
    cudaGetSymbolAddress((void**)&wht_lo, g_Wht_lo);

    // Phase 0: weight split + transpose
    {
        dim3 blk(32, 8);
        dim3 grid(RNN_H / 32, RNN_D / 32);
        convert_w_kernel<<<grid, blk>>>(Wx, wxt_hi, wxt_lo, RNN_D, RNN_H);
        convert_w_kernel<<<grid, blk>>>(Wh, wht_hi, wht_lo, RNN_H, RNN_H);
    }

    // Phase 1: out = x @ Wx + b
    {
        const int p1_smem = (2 * 2 * P1_ABUF + 2 * 2 * P1_BBUF) *
                            (int)sizeof(__nv_bfloat16);   // 61440
        cudaFuncSetAttribute(gemm_xw_hmma,
                             cudaFuncAttributeMaxDynamicSharedMemorySize,
                             p1_smem);
        dim3 grid(RNN_H / 128, (RNN_N * RNN_T) / 64);  // (8, 1024)
        gemm_xw_hmma<<<grid, 512, p1_smem>>>(x, b, out);
    }

    // Phase 2: persistent kernel over all 512 steps
    {
        const int smem_bytes =
            2 * (P2_BN * P2_LDB) * (int)sizeof(__nv_bfloat16) +      // Wh hi+lo
            4 * 2 * P2_ABUF * (int)sizeof(__nv_bfloat16) +           // A bufs
            4 * (P2_BM * P2_REDLD) * (int)sizeof(float);             // reduce
        cudaFuncSetAttribute(rnn_persistent,
                             cudaFuncAttributeMaxDynamicSharedMemorySize,
                             smem_bytes);
        rnn_persistent<<<P2_NCTAS, 512, smem_bytes>>>(h0, out);
    }
}